// round 11
// baseline (speedup 1.0000x reference)
#include <cuda_runtime.h>
#include <math.h>

// Depthwise 5x5 Gaussian blur, separable, barrier-free full-plane streaming.
// One warp = one whole 64x64 plane; lane owns columns 2l,2l+1. Vertical pass
// is a per-thread rolling 5-row window over a software-pipelined row stream
// (prefetch distance PD); horizontal pass on the vertical sum via +-1 lane
// shuffles. No smem, no __syncthreads; each input element read exactly once.
// x: [16, 256, 64, 64] f32, sigma: [1] f32.

#define HH 64
#define WW 64
#define TPB 128          // 4 warps = 4 planes per block
#define PD  6            // prefetch distance in rows

__global__ __launch_bounds__(TPB) void gauss5_kernel(const float* __restrict__ x,
                                                     const float* __restrict__ sigma_p,
                                                     float* __restrict__ out)
{
    const int tid   = threadIdx.x;
    const int lane  = tid & 31;                      // column pair (cols 2l, 2l+1)
    const int plane = blockIdx.x * (TPB / 32) + (tid >> 5);   // 0..4095

    const float2* gin  = reinterpret_cast<const float2*>(x)   + (long)plane * 2048;
    float2*       gout = reinterpret_cast<float2*>(out)       + (long)plane * 2048;

    // Gaussian taps (symmetric), center tap folded to 1.
    const float sigma = sigma_p[0];
    const float inv2s2 = 1.0f / (2.0f * sigma * sigma);
    const float g0 = expf(-4.0f * inv2s2);   // |d| = 2
    const float g1 = expf(-1.0f * inv2s2);   // |d| = 1
    const float s1 = 2.0f * (g0 + g1) + 1.0f;
    const float invn = 1.0f / (s1 * s1);
    // fold normalization into the vertical stage
    const float vg0 = g0 * invn;
    const float vg1 = g1 * invn;
    const float vg2 = invn;

    // in[j] holds input row (j - 2); rows -2,-1,64,65 are compile-time zeros.
    float2 in[68];

    // preload rows -2 .. (2 + PD)
    #pragma unroll
    for (int j = 0; j < 5 + PD; j++) {
        if (j < 2) in[j] = make_float2(0.f, 0.f);    // rows -2, -1
        else       in[j] = gin[(j - 2) * 32 + lane];
    }

    #pragma unroll
    for (int rr = 0; rr < HH; rr++) {
        // prefetch row (rr + 3 + PD); all predicates compile-time
        {
            const int j = rr + 5 + PD;
            if (j < 68) {
                const int r = j - 2;
                in[j] = (r < HH) ? gin[r * 32 + lane] : make_float2(0.f, 0.f);
            }
        }

        // vertical pass on rows rr-2 .. rr+2 (normalization folded in)
        float2 v;
        v.x = vg0 * (in[rr].x + in[rr+4].x) + vg1 * (in[rr+1].x + in[rr+3].x)
            + vg2 * in[rr+2].x;
        v.y = vg0 * (in[rr].y + in[rr+4].y) + vg1 * (in[rr+1].y + in[rr+3].y)
            + vg2 * in[rr+2].y;

        // horizontal pass on the vertical sum (in-warp shuffles)
        float px = __shfl_up_sync(0xffffffffu, v.x, 1);    // col 2l-2
        float py = __shfl_up_sync(0xffffffffu, v.y, 1);    // col 2l-1
        float nx = __shfl_down_sync(0xffffffffu, v.x, 1);  // col 2l+2
        float ny = __shfl_down_sync(0xffffffffu, v.y, 1);  // col 2l+3
        if (lane == 0)  { px = 0.0f; py = 0.0f; }          // left zero-pad
        if (lane == 31) { nx = 0.0f; ny = 0.0f; }          // right zero-pad

        float2 o;
        o.x = g0 * (px + nx) + g1 * (py + v.y) + v.x;
        o.y = g0 * (py + ny) + g1 * (v.x + nx) + v.y;
        __stcs(gout + rr * 32 + lane, o);
    }
}

extern "C" void kernel_launch(void* const* d_in, const int* in_sizes, int n_in,
                              void* d_out, int out_size) {
    const float* x = (const float*)d_in[0];
    const float* sigma = (const float*)d_in[1];
    float* out = (float*)d_out;
    int planes = in_sizes[0] / (HH * WW);            // 4096
    gauss5_kernel<<<planes / (TPB / 32), TPB>>>(x, sigma, out);
}

// round 12
// speedup vs baseline: 1.0976x; 1.0976x over previous
#include <cuda_runtime.h>
#include <math.h>

// Depthwise 5x5 Gaussian blur, separable, barrier-free column streaming.
// One warp = one 16-row x 64-col quarter-plane strip (loads 20 rows incl.
// halo); lane owns columns 2l,2l+1. Vertical pass: per-thread rolling 5-row
// window over a software-pipelined row stream (prefetch distance PD=8).
// Horizontal pass on the vertical sum via +-1 lane shuffles.
// No smem, no __syncthreads. x: [16, 256, 64, 64] f32, sigma: [1] f32.

#define HH 64
#define WW 64
#define TPB 256          // 8 warps = 8 strips per block
#define PD  8            // prefetch distance in rows

__global__ __launch_bounds__(TPB) void gauss5_kernel(const float* __restrict__ x,
                                                     const float* __restrict__ sigma_p,
                                                     float* __restrict__ out)
{
    const int tid   = threadIdx.x;
    const int lane  = tid & 31;                        // column pair (2l, 2l+1)
    const int gw    = blockIdx.x * (TPB / 32) + (tid >> 5);
    const int plane = gw >> 2;                         // 0..4095
    const int strip = gw & 3;                          // 16-row strip (0..3)

    const float2* gin  = reinterpret_cast<const float2*>(x)   + (long)plane * 2048;
    float2*       gout = reinterpret_cast<float2*>(out)       + (long)plane * 2048
                                                              + strip * 16 * 32;

    // Gaussian taps (symmetric), center tap folded to 1.
    const float sigma = sigma_p[0];
    const float inv2s2 = 1.0f / (2.0f * sigma * sigma);
    const float g0 = expf(-4.0f * inv2s2);   // |d| = 2
    const float g1 = expf(-1.0f * inv2s2);   // |d| = 1
    const float s1 = 2.0f * (g0 + g1) + 1.0f;
    const float invn = 1.0f / (s1 * s1);
    // fold normalization into the vertical stage
    const float vg0 = g0 * invn;
    const float vg1 = g1 * invn;
    const float vg2 = invn;

    const int row0 = strip * 16 - 2;         // input row held by in[0]

    // in[j] holds input row row0+j (j = 0..19); fully unrolled ring.
    float2 in[20];

    // preload rows 0 .. 4+PD (13 rows)
    #pragma unroll
    for (int j = 0; j < 5 + PD; j++) {
        int r = row0 + j;
        in[j] = (r >= 0 && r < HH) ? gin[r * 32 + lane] : make_float2(0.f, 0.f);
    }

    #pragma unroll
    for (int rr = 0; rr < 16; rr++) {
        // prefetch row rr + 5 + PD (compile-time bound check)
        if (rr + 5 + PD < 20) {
            const int j = rr + 5 + PD;
            int r = row0 + j;
            in[j] = (r >= 0 && r < HH) ? gin[r * 32 + lane] : make_float2(0.f, 0.f);
        }

        // vertical pass on rows rr-2 .. rr+2 (normalization folded in)
        float2 v;
        v.x = vg0 * (in[rr].x + in[rr+4].x) + vg1 * (in[rr+1].x + in[rr+3].x)
            + vg2 * in[rr+2].x;
        v.y = vg0 * (in[rr].y + in[rr+4].y) + vg1 * (in[rr+1].y + in[rr+3].y)
            + vg2 * in[rr+2].y;

        // horizontal pass on the vertical sum (in-warp shuffles)
        float px = __shfl_up_sync(0xffffffffu, v.x, 1);    // col 2l-2
        float py = __shfl_up_sync(0xffffffffu, v.y, 1);    // col 2l-1
        float nx = __shfl_down_sync(0xffffffffu, v.x, 1);  // col 2l+2
        float ny = __shfl_down_sync(0xffffffffu, v.y, 1);  // col 2l+3
        if (lane == 0)  { px = 0.0f; py = 0.0f; }          // left zero-pad
        if (lane == 31) { nx = 0.0f; ny = 0.0f; }          // right zero-pad

        float2 o;
        o.x = g0 * (px + nx) + g1 * (py + v.y) + v.x;
        o.y = g0 * (py + ny) + g1 * (v.x + nx) + v.y;
        __stcs(gout + rr * 32 + lane, o);
    }
}

extern "C" void kernel_launch(void* const* d_in, const int* in_sizes, int n_in,
                              void* d_out, int out_size) {
    const float* x = (const float*)d_in[0];
    const float* sigma = (const float*)d_in[1];
    float* out = (float*)d_out;
    int planes = in_sizes[0] / (HH * WW);            // 4096
    int warps  = planes * 4;                         // quarter-plane strips
    gauss5_kernel<<<warps / (TPB / 32), TPB>>>(x, sigma, out);
}